// round 4
// baseline (speedup 1.0000x reference)
#include <cuda_runtime.h>

// SpatialTransformer: trilinear warp of vol[0] ([160,192,224,2] f32) by dense
// shift field trf[0] ([160,192,224,3] f32). Out-of-domain clamped like the
// reference (loc clipped, loc0=clip(floor), loc1=clip(loc0+1), w_c0=loc1-loc).
//
// One block per z-row: blockDim.x = 224 (7 full warps), gridDim.x = 160*192.
// Every block's trf reads and out writes are row-aligned and fully coalesced;
// gathers stay within a 2x2-row neighborhood (~7.3 KB) for L1 reuse.

static constexpr int D0 = 160;
static constexpr int D1 = 192;
static constexpr int D2 = 224;

__global__ __launch_bounds__(D2) void st_warp_kernel(
    const float* __restrict__ vol,   // [D0,D1,D2,2]
    const float* __restrict__ trf,   // [D0,D1,D2,3]
    float2* __restrict__ out)        // [D0,D1,D2] of float2 (2 channels)
{
    int row = blockIdx.x;            // 0 .. D0*D1-1
    int z = threadIdx.x;             // 0 .. 223
    int y = row % D1;
    int x = row / D1;
    int i = row * D2 + z;            // flat voxel index

    // dense shift (stride-3 scalar loads; row-aligned base)
    float sx = __ldg(&trf[3 * i + 0]);
    float sy = __ldg(&trf[3 * i + 1]);
    float sz = __ldg(&trf[3 * i + 2]);

    const float mx = (float)(D0 - 1);
    const float my = (float)(D1 - 1);
    const float mz = (float)(D2 - 1);

    // clip absolute sample locations into domain
    float lx = fminf(fmaxf((float)x + sx, 0.0f), mx);
    float ly = fminf(fmaxf((float)y + sy, 0.0f), my);
    float lz = fminf(fmaxf((float)z + sz, 0.0f), mz);

    // corner-0 coordinate (floor, already in [0,max]); corner-1 clamped
    float fx0 = floorf(lx), fy0 = floorf(ly), fz0 = floorf(lz);
    float fx1 = fminf(fx0 + 1.0f, mx);
    float fy1 = fminf(fy0 + 1.0f, my);
    float fz1 = fminf(fz0 + 1.0f, mz);

    // reference weights: w_c0 = loc1 - loc, w_c1 = 1 - w_c0
    float wx0 = fx1 - lx, wx1 = 1.0f - wx0;
    float wy0 = fy1 - ly, wy1 = 1.0f - wy0;
    float wz0 = fz1 - lz, wz1 = 1.0f - wz0;

    int x0 = (int)fx0, x1 = (int)fx1;
    int y0 = (int)fy0, y1 = (int)fy1;
    int z0 = (int)fz0, z1 = (int)fz1;

    const float2* v2 = (const float2*)vol;   // [D0,D1,D2] of float2

    int bx0 = x0 * D1;
    int bx1 = x1 * D1;
    int r00 = (bx0 + y0) * D2;
    int r01 = (bx0 + y1) * D2;
    int r10 = (bx1 + y0) * D2;
    int r11 = (bx1 + y1) * D2;

    float2 c000 = __ldg(&v2[r00 + z0]);
    float2 c001 = __ldg(&v2[r00 + z1]);
    float2 c010 = __ldg(&v2[r01 + z0]);
    float2 c011 = __ldg(&v2[r01 + z1]);
    float2 c100 = __ldg(&v2[r10 + z0]);
    float2 c101 = __ldg(&v2[r10 + z1]);
    float2 c110 = __ldg(&v2[r11 + z0]);
    float2 c111 = __ldg(&v2[r11 + z1]);

    // nested lerp: z, then y, then x (per-dim weights sum to 1; matches the
    // reference's sum-of-8-corner-products up to fp reassociation)
    float a00x = wz0 * c000.x + wz1 * c001.x;
    float a00y = wz0 * c000.y + wz1 * c001.y;
    float a01x = wz0 * c010.x + wz1 * c011.x;
    float a01y = wz0 * c010.y + wz1 * c011.y;
    float a10x = wz0 * c100.x + wz1 * c101.x;
    float a10y = wz0 * c100.y + wz1 * c101.y;
    float a11x = wz0 * c110.x + wz1 * c111.x;
    float a11y = wz0 * c110.y + wz1 * c111.y;

    float b0x = wy0 * a00x + wy1 * a01x;
    float b0y = wy0 * a00y + wy1 * a01y;
    float b1x = wy0 * a10x + wy1 * a11x;
    float b1y = wy0 * a10y + wy1 * a11y;

    float2 o;
    o.x = wx0 * b0x + wx1 * b1x;
    o.y = wx0 * b0y + wx1 * b1y;
    out[i] = o;
}

extern "C" void kernel_launch(void* const* d_in, const int* in_sizes, int n_in,
                              void* d_out, int out_size)
{
    const float* vol = (const float*)d_in[0];   // [2,160,192,224,2]; batch 0 at base
    const float* trf = (const float*)d_in[1];   // [2,160,192,224,3]; batch 0 at base
    float2* out = (float2*)d_out;               // [160,192,224,2]

    st_warp_kernel<<<D0 * D1, D2>>>(vol, trf, out);
}